// round 2
// baseline (speedup 1.0000x reference)
#include <cuda_runtime.h>
#include <cuda_bf16.h>

#define NN 50000
#define EE 800000
#define EP (EE + NN)      // edges + self loops = 850000
#define FIN 64
#define FOUT 256          // HEADS*HID
#define NC 16

// ---------------- scratch (device globals; no allocations allowed) --------
__device__ float4 g_xh1[NN * 64];     // [N,256] layer1 features (as float4)
__device__ float4 g_out1[NN * 64];    // [N,256] layer1 aggregation output
__device__ float4 g_xh2[NN * 4];      // [N,16]  layer2 features
__device__ float4 g_a_src1[NN];       // [N,4]
__device__ float4 g_a_dst1[NN];       // [N,4]
__device__ float  g_a_src2[NN];
__device__ float  g_a_dst2[NN];
__device__ int    g_rowptr[NN + 1];
__device__ int    g_cnt[NN];
__device__ int    g_cur[NN];
__device__ int    g_col[EP];          // CSR: src node per incoming edge of dst
__device__ int    g_is64;             // 1 if edge_index is int64, 0 if int32

// ---------------- helpers -------------------------------------------------
__device__ __forceinline__ float wmax(float v) {
#pragma unroll
    for (int o = 16; o; o >>= 1) v = fmaxf(v, __shfl_xor_sync(0xffffffffu, v, o));
    return v;
}
__device__ __forceinline__ float wsum(float v) {
#pragma unroll
    for (int o = 16; o; o >>= 1) v += __shfl_xor_sync(0xffffffffu, v, o);
    return v;
}
__device__ __forceinline__ float lrelu(float e) { return e > 0.f ? e : 0.2f * e; }

__device__ __forceinline__ int clampN(int v) {
    return v < 0 ? 0 : (v >= NN ? NN - 1 : v);
}

// read edge entry i (0..2*EE-1) honoring detected dtype
__device__ __forceinline__ int edge_at(const void* ei, int i) {
    if (g_is64) return (int)((const long long*)ei)[i];
    return ((const int*)ei)[i];
}

// ---------------- dtype detect + zero -------------------------------------
__global__ void k_zero() {
    int i = blockIdx.x * blockDim.x + threadIdx.x;
    if (i == 0) g_is64 = 1;
    if (i < NN) { g_cnt[i] = 0; g_cur[i] = 0; }
}

// Interpret first EE elements as int64; if any is outside [0,NN) the buffer
// is actually int32. (int32 buffer has 2*EE elems = EE int64 slots, so these
// reads stay in-bounds either way.)
__global__ void k_detect(const long long* __restrict__ ei) {
    int i = blockIdx.x * blockDim.x + threadIdx.x;
    if (i >= EE) return;
    long long v = ei[i];
    if (v < 0 || v >= NN) g_is64 = 0;
}

// ---------------- CSR build -----------------------------------------------
__global__ void k_count(const void* __restrict__ ei) {
    int i = blockIdx.x * blockDim.x + threadIdx.x;
    if (i >= EP) return;
    int d = (i < EE) ? clampN(edge_at(ei, EE + i)) : (i - EE);
    atomicAdd(&g_cnt[d], 1);
}

__global__ void k_scan() {   // single block, 1024 threads
    __shared__ int sh[1024];
    __shared__ int carry;
    int t = threadIdx.x;
    if (t == 0) { carry = 0; g_rowptr[0] = 0; }
    __syncthreads();
    for (int base = 0; base < NN; base += 1024) {
        int i = base + t;
        int v = (i < NN) ? g_cnt[i] : 0;
        sh[t] = v; __syncthreads();
        for (int off = 1; off < 1024; off <<= 1) {
            int tv = (t >= off) ? sh[t - off] : 0;
            __syncthreads();
            sh[t] += tv;
            __syncthreads();
        }
        int inc = sh[t] + carry;
        if (i < NN) g_rowptr[i + 1] = inc;
        __syncthreads();
        if (t == 1023) carry = inc;
        __syncthreads();
    }
}

__global__ void k_fill(const void* __restrict__ ei) {
    int i = blockIdx.x * blockDim.x + threadIdx.x;
    if (i >= EP) return;
    int s, d;
    if (i < EE) { s = clampN(edge_at(ei, i)); d = clampN(edge_at(ei, EE + i)); }
    else        { s = i - EE;                 d = i - EE; }
    int pos = g_rowptr[d] + atomicAdd(&g_cur[d], 1);
    g_col[pos] = s;
}

// ---------------- layer 1 GEMM: xh1 = x @ W1 ------------------------------
__global__ void k_gemm1(const float* __restrict__ x, const float* __restrict__ W1) {
    __shared__ float xs[16][FIN];
    int row0 = blockIdx.x * 16;
    int t = threadIdx.x;                 // 256 threads; thread t owns column t
    for (int i = t; i < 16 * FIN; i += 256) {
        int r = i >> 6, c = i & 63;
        int gr = row0 + r;
        xs[r][c] = (gr < NN) ? x[gr * FIN + c] : 0.f;
    }
    __syncthreads();
    float acc[16];
#pragma unroll
    for (int r = 0; r < 16; r++) acc[r] = 0.f;
    for (int k = 0; k < FIN; k++) {
        float w = W1[k * FOUT + t];
#pragma unroll
        for (int r = 0; r < 16; r++) acc[r] += xs[r][k] * w;
    }
    float* xh = (float*)g_xh1;
#pragma unroll
    for (int r = 0; r < 16; r++) {
        int gr = row0 + r;
        if (gr < NN) xh[gr * FOUT + t] = acc[r];
    }
}

// ---------------- attention scalars layer1 --------------------------------
__global__ void k_att1(const float* __restrict__ as1, const float* __restrict__ ad1) {
    int i = blockIdx.x * blockDim.x + threadIdx.x;
    if (i >= NN * 4) return;
    int n = i >> 2, h = i & 3;
    const float* xp = (const float*)g_xh1 + n * FOUT + h * 64;
    const float* ap = as1 + h * 64;
    const float* dp = ad1 + h * 64;
    float s = 0.f, d = 0.f;
#pragma unroll
    for (int k = 0; k < 64; k++) { float v = xp[k]; s += v * ap[k]; d += v * dp[k]; }
    ((float*)g_a_src1)[i] = s;
    ((float*)g_a_dst1)[i] = d;
}

// ---------------- layer 1 aggregation (warp per dst node) -----------------
__global__ void k_agg1() {
    int warp = (blockIdx.x * blockDim.x + threadIdx.x) >> 5;
    int lane = threadIdx.x & 31;
    if (warp >= NN) return;
    int d = warp;
    int beg = g_rowptr[d], end = g_rowptr[d + 1];
    float4 adv = g_a_dst1[d];
    float ad0 = adv.x, ad1 = adv.y, ad2 = adv.z, ad3 = adv.w;

    float m0 = -1e30f, m1 = -1e30f, m2 = -1e30f, m3 = -1e30f;
    for (int k = beg + lane; k < end; k += 32) {
        float4 av = g_a_src1[g_col[k]];
        m0 = fmaxf(m0, lrelu(av.x + ad0));
        m1 = fmaxf(m1, lrelu(av.y + ad1));
        m2 = fmaxf(m2, lrelu(av.z + ad2));
        m3 = fmaxf(m3, lrelu(av.w + ad3));
    }
    m0 = wmax(m0); m1 = wmax(m1); m2 = wmax(m2); m3 = wmax(m3);

    float s0 = 0.f, s1 = 0.f, s2 = 0.f, s3 = 0.f;
    for (int k = beg + lane; k < end; k += 32) {
        float4 av = g_a_src1[g_col[k]];
        s0 += __expf(lrelu(av.x + ad0) - m0);
        s1 += __expf(lrelu(av.y + ad1) - m1);
        s2 += __expf(lrelu(av.z + ad2) - m2);
        s3 += __expf(lrelu(av.w + ad3) - m3);
    }
    s0 = wsum(s0); s1 = wsum(s1); s2 = wsum(s2); s3 = wsum(s3);
    float i0 = 1.f / (s0 + 1e-16f), i1 = 1.f / (s1 + 1e-16f);
    float i2 = 1.f / (s2 + 1e-16f), i3 = 1.f / (s3 + 1e-16f);

    // lane covers cols [4*lane .. 4*lane+3] (head h0) and [128+4*lane ..] (head h0+2)
    int h0 = lane >> 4;
    float adA = h0 ? ad1 : ad0, adB = h0 ? ad3 : ad2;
    float mA  = h0 ? m1  : m0,  mB  = h0 ? m3  : m2;
    float vA  = h0 ? i1  : i0,  vB  = h0 ? i3  : i2;

    float4 acc0 = {0.f, 0.f, 0.f, 0.f}, acc1 = {0.f, 0.f, 0.f, 0.f};
    const float* asf = (const float*)g_a_src1;
    for (int k = beg; k < end; k++) {
        int s = g_col[k];
        float eA = lrelu(asf[4 * s + h0] + adA);
        float eB = lrelu(asf[4 * s + 2 + h0] + adB);
        float alA = __expf(eA - mA) * vA;
        float alB = __expf(eB - mB) * vB;
        const float4* xp = g_xh1 + s * 64;
        float4 xa = xp[lane];
        float4 xb = xp[32 + lane];
        acc0.x += xa.x * alA; acc0.y += xa.y * alA; acc0.z += xa.z * alA; acc0.w += xa.w * alA;
        acc1.x += xb.x * alB; acc1.y += xb.y * alB; acc1.z += xb.z * alB; acc1.w += xb.w * alB;
    }
    float4* op = g_out1 + d * 64;
    op[lane] = acc0;
    op[32 + lane] = acc1;
}

// ---------------- layer 2 GEMM: h=elu(out1+b1); xh2=h@W2; a2 scalars ------
__global__ void k_gemm2(const float* __restrict__ b1, const float* __restrict__ W2,
                        const float* __restrict__ as2, const float* __restrict__ ad2) {
    __shared__ float W2s[FOUT * NC];
    __shared__ float hs[16][FOUT];
    __shared__ float xs2[16][NC + 1];
    __shared__ float a2s[NC], a2d[NC];
    int t = threadIdx.x;
    for (int i = t; i < FOUT * NC; i += 256) W2s[i] = W2[i];
    if (t < NC) { a2s[t] = as2[t]; a2d[t] = ad2[t]; }
    int row0 = blockIdx.x * 16;
    const float* o1 = (const float*)g_out1;
    for (int i = t; i < 16 * FOUT; i += 256) {
        int r = i >> 8, k = i & 255;
        int gr = row0 + r;
        float v = (gr < NN) ? o1[gr * FOUT + k] + b1[k] : 0.f;
        hs[r][k] = v > 0.f ? v : (__expf(v) - 1.f);
    }
    __syncthreads();
    int r = t >> 4, c = t & 15;
    int gr = row0 + r;
    float acc = 0.f;
#pragma unroll 8
    for (int k = 0; k < FOUT; k++) acc += hs[r][k] * W2s[k * NC + c];
    if (gr < NN) ((float*)g_xh2)[gr * NC + c] = acc;
    xs2[r][c] = acc;
    __syncthreads();
    if (c < 2 && gr < NN) {
        float s = 0.f;
#pragma unroll
        for (int j = 0; j < NC; j++) s += xs2[r][j] * (c ? a2d[j] : a2s[j]);
        if (c) g_a_dst2[gr] = s; else g_a_src2[gr] = s;
    }
}

// ---------------- layer 2 aggregation + bias + log_softmax ----------------
__global__ void k_agg2(const float* __restrict__ b2, float* __restrict__ out) {
    int warp = (blockIdx.x * blockDim.x + threadIdx.x) >> 5;
    int lane = threadIdx.x & 31;
    if (warp >= NN) return;
    int d = warp;
    int beg = g_rowptr[d], end = g_rowptr[d + 1];
    float adn = g_a_dst2[d];

    float m = -1e30f;
    for (int k = beg + lane; k < end; k += 32)
        m = fmaxf(m, lrelu(g_a_src2[g_col[k]] + adn));
    m = wmax(m);

    float ss = 0.f;
    for (int k = beg + lane; k < end; k += 32)
        ss += __expf(lrelu(g_a_src2[g_col[k]] + adn) - m);
    ss = wsum(ss);
    float inv = 1.f / (ss + 1e-16f);

    float acc[NC];
#pragma unroll
    for (int j = 0; j < NC; j++) acc[j] = 0.f;
    for (int k = beg + lane; k < end; k += 32) {
        int s = g_col[k];
        float al = __expf(lrelu(g_a_src2[s] + adn) - m) * inv;
        const float4* xp = g_xh2 + s * 4;
        float4 v0 = xp[0], v1 = xp[1], v2 = xp[2], v3 = xp[3];
        acc[0] += v0.x * al; acc[1] += v0.y * al; acc[2] += v0.z * al; acc[3] += v0.w * al;
        acc[4] += v1.x * al; acc[5] += v1.y * al; acc[6] += v1.z * al; acc[7] += v1.w * al;
        acc[8] += v2.x * al; acc[9] += v2.y * al; acc[10] += v2.z * al; acc[11] += v2.w * al;
        acc[12] += v3.x * al; acc[13] += v3.y * al; acc[14] += v3.z * al; acc[15] += v3.w * al;
    }
#pragma unroll
    for (int j = 0; j < NC; j++) acc[j] = wsum(acc[j]);

    float l[NC];
    float mm = -1e30f;
#pragma unroll
    for (int j = 0; j < NC; j++) { l[j] = acc[j] + b2[j]; mm = fmaxf(mm, l[j]); }
    float ls = 0.f;
#pragma unroll
    for (int j = 0; j < NC; j++) ls += __expf(l[j] - mm);
    ls = logf(ls) + mm;
    float v = l[0];
#pragma unroll
    for (int j = 1; j < NC; j++) if (lane == j) v = l[j];
    if (lane < NC) out[d * NC + lane] = v - ls;
}

// ---------------- launch ---------------------------------------------------
extern "C" void kernel_launch(void* const* d_in, const int* in_sizes, int n_in,
                              void* d_out, int out_size) {
    const float* x   = (const float*)d_in[0];
    const void*  ei  = d_in[1];
    const float* W1  = (const float*)d_in[2];
    const float* as1 = (const float*)d_in[3];
    const float* ad1 = (const float*)d_in[4];
    const float* b1  = (const float*)d_in[5];
    const float* W2  = (const float*)d_in[6];
    const float* as2 = (const float*)d_in[7];
    const float* ad2 = (const float*)d_in[8];
    const float* b2  = (const float*)d_in[9];
    float* out = (float*)d_out;

    k_zero  <<<(NN + 255) / 256, 256>>>();
    k_detect<<<(EE + 255) / 256, 256>>>((const long long*)ei);
    k_count <<<(EP + 255) / 256, 256>>>(ei);
    k_scan  <<<1, 1024>>>();
    k_fill  <<<(EP + 255) / 256, 256>>>(ei);
    k_gemm1 <<<(NN + 15) / 16, 256>>>(x, W1);
    k_att1  <<<(NN * 4 + 127) / 128, 128>>>(as1, ad1);
    k_agg1  <<<(NN + 7) / 8, 256>>>();
    k_gemm2 <<<(NN + 15) / 16, 256>>>(b1, W2, as2, ad2);
    k_agg2  <<<(NN + 7) / 8, 256>>>(b2, out);
}

// round 5
// speedup vs baseline: 1.1687x; 1.1687x over previous
#include <cuda_runtime.h>
#include <cuda_bf16.h>

#define NN 50000
#define EE 800000
#define EP (EE + NN)      // edges + self loops = 850000
#define FIN 64
#define FOUT 256          // HEADS*HID
#define NC 16
#define SCAN_B 512
#define SCAN_NB ((NN + SCAN_B - 1) / SCAN_B)   // 98

// ---------------- scratch (device globals; no allocations allowed) --------
__device__ float4 g_xh1[NN * 64];     // [N,256] layer1 features (as float4)
__device__ float4 g_out1[NN * 64];    // [N,256] layer1 aggregation output
__device__ float4 g_xh2[NN * 4];      // [N,16]  layer2 features
__device__ float4 g_a_src1[NN];       // [N,4]
__device__ float4 g_a_dst1[NN];       // [N,4]
__device__ float  g_a_src2[NN];
__device__ float  g_a_dst2[NN];
__device__ int    g_rowptr[NN + 1];
__device__ int    g_cnt[NN];
__device__ int    g_cur[NN];
__device__ int    g_col[EP];          // CSR: src node per incoming edge of dst
__device__ int    g_is64;             // 1 if edge_index is int64, 0 if int32
__device__ int    g_bsum[SCAN_NB];
__device__ int    g_boff[SCAN_NB];

// ---------------- helpers -------------------------------------------------
__device__ __forceinline__ float wmax(float v) {
#pragma unroll
    for (int o = 16; o; o >>= 1) v = fmaxf(v, __shfl_xor_sync(0xffffffffu, v, o));
    return v;
}
__device__ __forceinline__ float wsum(float v) {
#pragma unroll
    for (int o = 16; o; o >>= 1) v += __shfl_xor_sync(0xffffffffu, v, o);
    return v;
}
__device__ __forceinline__ float lrelu(float e) { return e > 0.f ? e : 0.2f * e; }

__device__ __forceinline__ int clampN(int v) {
    return v < 0 ? 0 : (v >= NN ? NN - 1 : v);
}

__device__ __forceinline__ int edge_at(const void* ei, int i) {
    if (g_is64) return (int)((const long long*)ei)[i];
    return ((const int*)ei)[i];
}

// ---------------- dtype detect + zero -------------------------------------
__global__ void k_zero() {
    int i = blockIdx.x * blockDim.x + threadIdx.x;
    if (i == 0) g_is64 = 1;
    if (i < NN) { g_cnt[i] = 0; g_cur[i] = 0; }
}

__global__ void k_detect(const long long* __restrict__ ei) {
    int i = blockIdx.x * blockDim.x + threadIdx.x;
    if (i >= EE) return;
    long long v = ei[i];
    if (v < 0 || v >= NN) g_is64 = 0;
}

// ---------------- CSR build -----------------------------------------------
__global__ void k_count(const void* __restrict__ ei) {
    int i = blockIdx.x * blockDim.x + threadIdx.x;
    if (i >= EP) return;
    int d = (i < EE) ? clampN(edge_at(ei, EE + i)) : (i - EE);
    atomicAdd(&g_cnt[d], 1);
}

// block-level inclusive scan; writes per-block inclusive into rowptr[i+1],
// block total into g_bsum
__global__ void k_scan1() {
    __shared__ int sh[SCAN_B];
    int t = threadIdx.x, b = blockIdx.x;
    int i = b * SCAN_B + t;
    int v = (i < NN) ? g_cnt[i] : 0;
    sh[t] = v; __syncthreads();
#pragma unroll
    for (int off = 1; off < SCAN_B; off <<= 1) {
        int tv = (t >= off) ? sh[t - off] : 0;
        __syncthreads();
        sh[t] += tv;
        __syncthreads();
    }
    if (i < NN) g_rowptr[i + 1] = sh[t];
    if (t == SCAN_B - 1) g_bsum[b] = sh[t];
}

__global__ void k_scan2() {   // 1 block
    __shared__ int sh[SCAN_NB];
    int t = threadIdx.x;
    if (t < SCAN_NB) sh[t] = g_bsum[t];
    __syncthreads();
    if (t == 0) {
        int run = 0;
        for (int j = 0; j < SCAN_NB; j++) { g_boff[j] = run; run += sh[j]; }
    }
}

__global__ void k_scan3() {
    int t = threadIdx.x, b = blockIdx.x;
    int i = b * SCAN_B + t;
    if (i < NN) g_rowptr[i + 1] += g_boff[b];
    if (i == 0) g_rowptr[0] = 0;
}

__global__ void k_fill(const void* __restrict__ ei) {
    int i = blockIdx.x * blockDim.x + threadIdx.x;
    if (i >= EP) return;
    int s, d;
    if (i < EE) { s = clampN(edge_at(ei, i)); d = clampN(edge_at(ei, EE + i)); }
    else        { s = i - EE;                 d = i - EE; }
    int pos = g_rowptr[d] + atomicAdd(&g_cur[d], 1);
    g_col[pos] = s;
}

// ---------------- layer 1 GEMM: xh1 = x @ W1 ------------------------------
__global__ void k_gemm1(const float* __restrict__ x, const float* __restrict__ W1) {
    __shared__ float xs[16][FIN];
    int row0 = blockIdx.x * 16;
    int t = threadIdx.x;                 // 256 threads; thread t owns column t
    for (int i = t; i < 16 * FIN; i += 256) {
        int r = i >> 6, c = i & 63;
        int gr = row0 + r;
        xs[r][c] = (gr < NN) ? x[gr * FIN + c] : 0.f;
    }
    __syncthreads();
    float acc[16];
#pragma unroll
    for (int r = 0; r < 16; r++) acc[r] = 0.f;
    for (int k = 0; k < FIN; k++) {
        float w = W1[k * FOUT + t];
#pragma unroll
        for (int r = 0; r < 16; r++) acc[r] += xs[r][k] * w;
    }
    float* xh = (float*)g_xh1;
#pragma unroll
    for (int r = 0; r < 16; r++) {
        int gr = row0 + r;
        if (gr < NN) xh[gr * FOUT + t] = acc[r];
    }
}

// ---------------- attention scalars layer1 --------------------------------
__global__ void k_att1(const float* __restrict__ as1, const float* __restrict__ ad1) {
    int i = blockIdx.x * blockDim.x + threadIdx.x;
    if (i >= NN * 4) return;
    int n = i >> 2, h = i & 3;
    const float* xp = (const float*)g_xh1 + n * FOUT + h * 64;
    const float* ap = as1 + h * 64;
    const float* dp = ad1 + h * 64;
    float s = 0.f, d = 0.f;
#pragma unroll
    for (int k = 0; k < 64; k++) { float v = xp[k]; s += v * ap[k]; d += v * dp[k]; }
    ((float*)g_a_src1)[i] = s;
    ((float*)g_a_dst1)[i] = d;
}

// ---------------- layer 1 aggregation: single fused online pass -----------
// warp per dst node; one-deep software pipeline on the gathers.
// Lane covers cols [4*lane..] (head h0=lane>>4) and [128+4*lane..] (h0+2).
// Lanes sharing h0 track identical (m,s) replicas -> no shuffles needed.
__global__ void k_agg1() {
    int warp = (blockIdx.x * blockDim.x + threadIdx.x) >> 5;
    int lane = threadIdx.x & 31;
    if (warp >= NN) return;
    int d = warp;
    int beg = g_rowptr[d], end = g_rowptr[d + 1];   // end > beg (self-loop)
    float4 adv = g_a_dst1[d];
    int h0 = lane >> 4;
    float adA = h0 ? adv.y : adv.x;
    float adB = h0 ? adv.w : adv.z;

    float mA = -1e30f, mB = -1e30f, sA = 0.f, sB = 0.f;
    float4 acc0 = {0.f, 0.f, 0.f, 0.f}, acc1 = {0.f, 0.f, 0.f, 0.f};

    // prologue: fetch edge 'beg'
    int sc = g_col[beg];
    float4 av = g_a_src1[sc];
    const float4* xp = g_xh1 + sc * 64;
    float4 xa = xp[lane];
    float4 xb = xp[32 + lane];

    for (int k = beg; k < end; k++) {
        float4 av_c = av, xa_c = xa, xb_c = xb;
        if (k + 1 < end) {                       // prefetch next edge
            int sn = g_col[k + 1];
            av = g_a_src1[sn];
            const float4* xpn = g_xh1 + sn * 64;
            xa = xpn[lane];
            xb = xpn[32 + lane];
        }
        float eA = lrelu((h0 ? av_c.y : av_c.x) + adA);
        float eB = lrelu((h0 ? av_c.w : av_c.z) + adB);
        float mAn = fmaxf(mA, eA), mBn = fmaxf(mB, eB);
        float cA = __expf(mA - mAn), cB = __expf(mB - mBn);
        float pA = __expf(eA - mAn), pB = __expf(eB - mBn);
        sA = sA * cA + pA;
        sB = sB * cB + pB;
        acc0.x = acc0.x * cA + xa_c.x * pA;
        acc0.y = acc0.y * cA + xa_c.y * pA;
        acc0.z = acc0.z * cA + xa_c.z * pA;
        acc0.w = acc0.w * cA + xa_c.w * pA;
        acc1.x = acc1.x * cB + xb_c.x * pB;
        acc1.y = acc1.y * cB + xb_c.y * pB;
        acc1.z = acc1.z * cB + xb_c.z * pB;
        acc1.w = acc1.w * cB + xb_c.w * pB;
        mA = mAn; mB = mBn;
    }
    float iA = 1.f / (sA + 1e-16f);
    float iB = 1.f / (sB + 1e-16f);
    acc0.x *= iA; acc0.y *= iA; acc0.z *= iA; acc0.w *= iA;
    acc1.x *= iB; acc1.y *= iB; acc1.z *= iB; acc1.w *= iB;
    float4* op = g_out1 + d * 64;
    op[lane] = acc0;
    op[32 + lane] = acc1;
}

// ---------------- layer 2 GEMM: h=elu(out1+b1); xh2=h@W2; a2 scalars ------
__global__ void k_gemm2(const float* __restrict__ b1, const float* __restrict__ W2,
                        const float* __restrict__ as2, const float* __restrict__ ad2) {
    __shared__ float W2s[FOUT * NC];
    __shared__ float hs[16][FOUT];
    __shared__ float xs2[16][NC + 1];
    __shared__ float a2s[NC], a2d[NC];
    int t = threadIdx.x;
    for (int i = t; i < FOUT * NC; i += 256) W2s[i] = W2[i];
    if (t < NC) { a2s[t] = as2[t]; a2d[t] = ad2[t]; }
    int row0 = blockIdx.x * 16;
    const float* o1 = (const float*)g_out1;
    for (int i = t; i < 16 * FOUT; i += 256) {
        int r = i >> 8, k = i & 255;
        int gr = row0 + r;
        float v = (gr < NN) ? o1[gr * FOUT + k] + b1[k] : 0.f;
        hs[r][k] = v > 0.f ? v : (__expf(v) - 1.f);
    }
    __syncthreads();
    int r = t >> 4, c = t & 15;
    int gr = row0 + r;
    float acc = 0.f;
#pragma unroll 8
    for (int k = 0; k < FOUT; k++) acc += hs[r][k] * W2s[k * NC + c];
    if (gr < NN) ((float*)g_xh2)[gr * NC + c] = acc;
    xs2[r][c] = acc;
    __syncthreads();
    if (c < 2 && gr < NN) {
        float s = 0.f;
#pragma unroll
        for (int j = 0; j < NC; j++) s += xs2[r][j] * (c ? a2d[j] : a2s[j]);
        if (c) g_a_dst2[gr] = s; else g_a_src2[gr] = s;
    }
}

// ---------------- layer 2 aggregation (fused online) + log_softmax --------
__global__ void k_agg2(const float* __restrict__ b2, float* __restrict__ out) {
    int warp = (blockIdx.x * blockDim.x + threadIdx.x) >> 5;
    int lane = threadIdx.x & 31;
    if (warp >= NN) return;
    int d = warp;
    int beg = g_rowptr[d], end = g_rowptr[d + 1];
    float adn = g_a_dst2[d];

    float m = -1e30f, ssum = 0.f;
    float acc[NC];
#pragma unroll
    for (int j = 0; j < NC; j++) acc[j] = 0.f;

    for (int k = beg + lane; k < end; k += 32) {
        int s = g_col[k];
        float e = lrelu(g_a_src2[s] + adn);
        float mn = fmaxf(m, e);
        float c = __expf(m - mn);
        float p = __expf(e - mn);
        ssum = ssum * c + p;
        const float4* xp = g_xh2 + s * 4;
        float4 v0 = xp[0], v1 = xp[1], v2 = xp[2], v3 = xp[3];
        acc[0] = acc[0] * c + v0.x * p;  acc[1] = acc[1] * c + v0.y * p;
        acc[2] = acc[2] * c + v0.z * p;  acc[3] = acc[3] * c + v0.w * p;
        acc[4] = acc[4] * c + v1.x * p;  acc[5] = acc[5] * c + v1.y * p;
        acc[6] = acc[6] * c + v1.z * p;  acc[7] = acc[7] * c + v1.w * p;
        acc[8] = acc[8] * c + v2.x * p;  acc[9] = acc[9] * c + v2.y * p;
        acc[10] = acc[10] * c + v2.z * p; acc[11] = acc[11] * c + v2.w * p;
        acc[12] = acc[12] * c + v3.x * p; acc[13] = acc[13] * c + v3.y * p;
        acc[14] = acc[14] * c + v3.z * p; acc[15] = acc[15] * c + v3.w * p;
        m = mn;
    }
    // merge per-lane partials
    float M = wmax(m);
    float corr = __expf(m - M);
    ssum = wsum(ssum * corr);
#pragma unroll
    for (int j = 0; j < NC; j++) acc[j] = wsum(acc[j] * corr);
    float inv = 1.f / (ssum + 1e-16f);

    float l[NC];
    float mm = -1e30f;
#pragma unroll
    for (int j = 0; j < NC; j++) { l[j] = acc[j] * inv + b2[j]; mm = fmaxf(mm, l[j]); }
    float ls = 0.f;
#pragma unroll
    for (int j = 0; j < NC; j++) ls += __expf(l[j] - mm);
    ls = logf(ls) + mm;
    float v = l[0];
#pragma unroll
    for (int j = 1; j < NC; j++) if (lane == j) v = l[j];
    if (lane < NC) out[d * NC + lane] = v - ls;
}

// ---------------- launch ---------------------------------------------------
extern "C" void kernel_launch(void* const* d_in, const int* in_sizes, int n_in,
                              void* d_out, int out_size) {
    const float* x   = (const float*)d_in[0];
    const void*  ei  = d_in[1];
    const float* W1  = (const float*)d_in[2];
    const float* as1 = (const float*)d_in[3];
    const float* ad1 = (const float*)d_in[4];
    const float* b1  = (const float*)d_in[5];
    const float* W2  = (const float*)d_in[6];
    const float* as2 = (const float*)d_in[7];
    const float* ad2 = (const float*)d_in[8];
    const float* b2  = (const float*)d_in[9];
    float* out = (float*)d_out;

    k_zero  <<<(NN + 255) / 256, 256>>>();
    k_detect<<<(EE + 255) / 256, 256>>>((const long long*)ei);
    k_count <<<(EP + 255) / 256, 256>>>(ei);
    k_scan1 <<<SCAN_NB, SCAN_B>>>();
    k_scan2 <<<1, 128>>>();
    k_scan3 <<<SCAN_NB, SCAN_B>>>();
    k_fill  <<<(EP + 255) / 256, 256>>>(ei);
    k_gemm1 <<<(NN + 15) / 16, 256>>>(x, W1);
    k_att1  <<<(NN * 4 + 127) / 128, 128>>>(as1, ad1);
    k_agg1  <<<(NN + 7) / 8, 256>>>();
    k_gemm2 <<<(NN + 15) / 16, 256>>>(b1, W2, as2, ad2);
    k_agg2  <<<(NN + 7) / 8, 256>>>(b2, out);
}